// round 4
// baseline (speedup 1.0000x reference)
#include <cuda_runtime.h>

#define HID    64
#define BATCH  16384
#define NSTEPS 100
#define DT     0.01f

__device__ float g_pA[128];
__device__ float g_pB[128];

typedef unsigned long long ull;

__device__ __forceinline__ float exact_tanh(float v) {
    float av = fabsf(v);
    float e  = __expf(-2.0f * av);
    float r  = __fdividef(1.0f - e, 1.0f + e);
    return copysignf(r, v);
}
__device__ __forceinline__ float tanh_ap(float x) {
    float y; asm("tanh.approx.f32 %0, %1;" : "=f"(y) : "f"(x)); return y;
}
__device__ __forceinline__ ull pack2(float lo, float hi) {
    ull r; asm("mov.b64 %0, {%1, %2};" : "=l"(r) : "f"(lo), "f"(hi)); return r;
}
__device__ __forceinline__ void unpack2(ull v, float& lo, float& hi) {
    asm("mov.b64 {%0, %1}, %2;" : "=f"(lo), "=f"(hi) : "l"(v));
}
__device__ __forceinline__ void ffma2(ull& d, ull a, ull b) {
    asm("fma.rn.f32x2 %0, %1, %2, %0;" : "+l"(d) : "l"(a), "l"(b));
}

// ---------------------------------------------------------------------------
// Fused kernel: per-block scalar prep (p0, dp0, pi0) + persistent simulation.
// Sample split across lane pairs (L, L^16): each lane owns 32 of 64 layer-2
// output units; partials combined via shfl. 256 thr/block -> 2 warps/SMSP.
// ---------------------------------------------------------------------------
__global__ void __launch_bounds__(256) sim_kernel(
    const float* __restrict__ dw,
    const float* __restrict__ X0, const float* __restrict__ R0,
    const float* __restrict__ pW1, const float* __restrict__ pb1,
    const float* __restrict__ pW2, const float* __restrict__ pb2,
    const float* __restrict__ pW3, const float* __restrict__ pb3,
    const float* __restrict__ qW1, const float* __restrict__ qb1,
    const float* __restrict__ qW2, const float* __restrict__ qb2,
    const float* __restrict__ qW3, const float* __restrict__ qb3,
    float* __restrict__ out)
{
    __shared__ __align__(16) float4 sW1q[HID];        // {w_t, w_x, w_r, b1}
    __shared__ __align__(16) ull    sW2p[HID * 32];   // [k][half*16 + 2*q8 + {0,1}]
    __shared__ ull   sb2h[2][16];
    __shared__ float sW3f[HID];
    __shared__ float sb3s, s_p0, s_dp0, s_pi0;
    __shared__ float ph1[HID], pd1[HID], ptA[HID], ptB[HID];
    __shared__ float redA[8], redB[8];

    const int tid  = threadIdx.x;
    const int lane = tid & 31;
    const int wid  = tid >> 5;
    const int half = lane >> 4;          // which 32-unit half this lane owns
    const int sl   = lane & 15;          // sample-within-warp

    const float x0v = X0[0], r0v = R0[0];

    // ---- load + pack q-net weights into shared ----
    for (int k = tid; k < HID; k += 256) {
        sW1q[k] = make_float4(qW1[k], qW1[HID + k], qW1[2 * HID + k], qb1[k]);
        sW3f[k] = qW3[k];
    }
    // row k occupies sW2p[k*32 .. k*32+31]; half h uses [k*32 + 16h .. +16h+15]
    for (int idx = tid; idx < HID * 16; idx += 256) {
        int q8 = idx & 7, h = (idx >> 3) & 1, k = idx >> 4;
        int c  = 32 * h + 4 * q8;
        sW2p[k * 32 + 16 * h + 2 * q8 + 0] = pack2(qW2[k * HID + c + 0], qW2[k * HID + c + 1]);
        sW2p[k * 32 + 16 * h + 2 * q8 + 1] = pack2(qW2[k * HID + c + 2], qW2[k * HID + c + 3]);
    }
    if (tid < 16) {
        sb2h[0][tid] = pack2(qb2[2 * tid],      qb2[2 * tid + 1]);
        sb2h[1][tid] = pack2(qb2[32 + 2 * tid], qb2[32 + 2 * tid + 1]);
    }
    if (tid == 0) sb3s = qb3[0];

    // ---- per-block scalar prep (threads 0..63), exact tanh ----
    if (tid < HID) {
        int j = tid;
        float a = pW1[HID + j] * x0v + pW1[2 * HID + j] * r0v + pb1[j];
        float h = exact_tanh(a);
        ph1[j] = h;
        pd1[j] = (1.0f - h * h) * pW1[HID + j];
        float aq = qW1[HID + j] * x0v + qW1[2 * HID + j] * r0v + qb1[j];
        ptA[j] = exact_tanh(aq);   // q-net h1
    }
    __syncthreads();

    float pa = 0.0f, qa = 0.0f, db = 0.0f;
    if (tid < HID) {
        int j = tid;
        float acc = pb2[j], dacc = 0.0f, accq = qb2[j];
        #pragma unroll 16
        for (int k = 0; k < HID; ++k) {
            float w = pW2[k * HID + j];
            acc  += ph1[k] * w;
            dacc += pd1[k] * w;
            accq += ptA[k] * qW2[k * HID + j];
        }
        float h2 = exact_tanh(acc);
        float d2 = (1.0f - h2 * h2) * dacc;
        pa = h2 * pW3[j];
        db = d2 * pW3[j];
        qa = exact_tanh(accq) * qW3[j];
    }
    __syncthreads();
    if (tid < HID) { ph1[tid] = pa; pd1[tid] = qa; ptB[tid] = db; }
    __syncthreads();
    if (tid == 0) {
        float s = pb3[0], sd = 0.0f, sq = qb3[0];
        for (int k = 0; k < HID; ++k) { s += ph1[k]; sd += ptB[k]; sq += pd1[k]; }
        s_p0 = s; s_dp0 = sd; s_pi0 = sq;
    }
    __syncthreads();

    const float p0  = s_p0;
    const float dp0 = s_dp0;
    const float pi0 = s_pi0;

    const int b = blockIdx.x * 128 + wid * 16 + sl;
    const float* __restrict__ dwp = dw + b * NSTEPS;

    const float C_ADT  = 0.05f * 0.01f;
    const float C_STDT = 0.2f * 0.3f * 0.01f;
    const float SIG    = 0.2f;
    const float BEFF   = 0.1f;
    const float C_R1   = 0.02f - 0.5f * 0.1f * 0.1f;
    const float C_P1   = -(0.05f + 0.5f * 0.3f * 0.3f);
    const float TH     = 0.3f;

    if (half == 0) {
        unsigned base = (unsigned)b * 5u;
        out[base + 0] = x0v; out[base + 1] = r0v; out[base + 2] = pi0;
        out[base + 3] = -p0; out[base + 4] = -dp0;
    }

    float x = x0v, mn = x0v, W = 0.0f, pi = pi0;
    float Rv = r0v, p = p0;

    const ull* __restrict__ wbase = sW2p + half * 16;
    const float* __restrict__ w3h = sW3f + half * 32;

    #pragma unroll 1
    for (int i = 1; i <= NSTEPS; ++i) {
        float dwi = dwp[i - 1];
        x = x + x * C_ADT + pi * C_STDT + pi * SIG * dwi;
        mn = fminf(mn, x);
        W += dwi;
        float t = (float)i * DT;
        Rv = r0v * __expf(C_R1 * t + BEFF * W);
        p  = p0  * __expf(C_P1 * t - TH * W);

        if (i < NSTEPS) {
            float s0 = 2.0f * t;

            ull acc[16];
            #pragma unroll
            for (int q = 0; q < 16; ++q) acc[q] = sb2h[half][q];

            #pragma unroll 4
            for (int k = 0; k < HID; ++k) {
                float4 w1 = sW1q[k];
                float a1 = fmaf(w1.x, s0, w1.w);
                a1 = fmaf(w1.y, x,  a1);
                a1 = fmaf(w1.z, Rv, a1);
                float h = tanh_ap(a1);
                ull hh = pack2(h, h);
                const ulonglong2* wr = (const ulonglong2*)(wbase + k * 32);
                #pragma unroll
                for (int q8 = 0; q8 < 8; ++q8) {
                    ulonglong2 w = wr[q8];
                    ffma2(acc[2 * q8 + 0], hh, w.x);
                    ffma2(acc[2 * q8 + 1], hh, w.y);
                }
            }

            float o0 = 0.0f, o1 = 0.0f, o2 = 0.0f, o3 = 0.0f;
            #pragma unroll
            for (int q = 0; q < 16; q += 2) {
                float a0, a1f, a2, a3;
                unpack2(acc[q],     a0, a1f);
                unpack2(acc[q + 1], a2, a3);
                o0 = fmaf(tanh_ap(a0),  w3h[2 * q + 0], o0);
                o1 = fmaf(tanh_ap(a1f), w3h[2 * q + 1], o1);
                o2 = fmaf(tanh_ap(a2),  w3h[2 * q + 2], o2);
                o3 = fmaf(tanh_ap(a3),  w3h[2 * q + 3], o3);
            }
            float opart = (o0 + o1) + (o2 + o3);
            float other = __shfl_xor_sync(0xffffffffu, opart, 16);
            pi = (opart + other) + sb3s;
        }
        if (half == 0) {
            unsigned base = ((unsigned)i * BATCH + (unsigned)b) * 5u;
            out[base + 0] = x;  out[base + 1] = Rv; out[base + 2] = pi;
            out[base + 3] = -p; out[base + 4] = -dp0;
        }
    }

    // ---- per-sample loss terms (identical in both halves) ----
    float xc  = fmaxf(x, 1e-6f);
    float ux  = Rv * rsqrtf(xc);
    float uv  = 2.0f * Rv * sqrtf(xc);
    float dpn = fmaxf(1e-6f - mn, 0.0f);
    float pen = 100.0f * dpn * dpn;
    float aa  = p + ux; aa = aa * aa + pen;
    float bb  = -uv + pen;

    // keep only half==0 contribution (halves are duplicates)
    if (half != 0) { aa = 0.0f; bb = 0.0f; }
    #pragma unroll
    for (int s = 16; s > 0; s >>= 1) {
        aa += __shfl_xor_sync(0xffffffffu, aa, s);
        bb += __shfl_xor_sync(0xffffffffu, bb, s);
    }
    if (lane == 0) { redA[wid] = aa; redB[wid] = bb; }
    __syncthreads();
    if (tid == 0) {
        float sA = 0.0f, sB = 0.0f;
        #pragma unroll
        for (int w = 0; w < 8; ++w) { sA += redA[w]; sB += redB[w]; }
        g_pA[blockIdx.x] = sA; g_pB[blockIdx.x] = sB;
    }
}

// ---------------------------------------------------------------------------
// Deterministic final reduction of the 128 block partials -> two losses.
// ---------------------------------------------------------------------------
__global__ void finalize_kernel(float* __restrict__ out)
{
    __shared__ float rA[128], rB[128];
    int tid = threadIdx.x;
    rA[tid] = g_pA[tid]; rB[tid] = g_pB[tid];
    __syncthreads();
    for (int s = 64; s > 0; s >>= 1) {
        if (tid < s) { rA[tid] += rA[tid + s]; rB[tid] += rB[tid + s]; }
        __syncthreads();
    }
    if (tid == 0) {
        float lp  = rA[0] / (float)BATCH;
        float lpi = lp + rB[0] / (float)BATCH;
        unsigned base = (unsigned)(NSTEPS + 1) * BATCH * 5u;
        out[base + 0] = lp;
        out[base + 1] = lpi;
    }
}

extern "C" void kernel_launch(void* const* d_in, const int* in_sizes, int n_in,
                              void* d_out, int out_size)
{
    const float* dw  = (const float*)d_in[0];
    const float* X0  = (const float*)d_in[1];
    const float* R0  = (const float*)d_in[2];
    const float* pW1 = (const float*)d_in[3];  const float* pb1 = (const float*)d_in[4];
    const float* pW2 = (const float*)d_in[5];  const float* pb2 = (const float*)d_in[6];
    const float* pW3 = (const float*)d_in[7];  const float* pb3 = (const float*)d_in[8];
    const float* qW1 = (const float*)d_in[9];  const float* qb1 = (const float*)d_in[10];
    const float* qW2 = (const float*)d_in[11]; const float* qb2 = (const float*)d_in[12];
    const float* qW3 = (const float*)d_in[13]; const float* qb3 = (const float*)d_in[14];
    float* out = (float*)d_out;

    sim_kernel<<<128, 256>>>(dw, X0, R0, pW1, pb1, pW2, pb2, pW3, pb3,
                             qW1, qb1, qW2, qb2, qW3, qb3, out);
    finalize_kernel<<<1, 128>>>(out);
}

// round 5
// speedup vs baseline: 1.5144x; 1.5144x over previous
#include <cuda_runtime.h>
#include <cuda_bf16.h>

#define HID    64
#define BATCH  16384
#define NSTEPS 100
#define DT     0.01f

__device__ float g_pA[128];
__device__ float g_pB[128];

__device__ __forceinline__ float exact_tanh(float v) {
    float av = fabsf(v);
    float e  = __expf(-2.0f * av);
    float r  = __fdividef(1.0f - e, 1.0f + e);
    return copysignf(r, v);
}
__device__ __forceinline__ float tanh_ap(float x) {
    float y; asm("tanh.approx.f32 %0, %1;" : "=f"(y) : "f"(x)); return y;
}
// pack two floats as bf16x2 (first arg -> low 16 bits)
__device__ __forceinline__ unsigned pack_bf2(float lo, float hi) {
    __nv_bfloat162 v = __floats2bfloat162_rn(lo, hi);
    return *reinterpret_cast<unsigned*>(&v);
}
__device__ __forceinline__ void mma_bf16(float& c0, float& c1, float& c2, float& c3,
                                         unsigned a0, unsigned a1, unsigned a2, unsigned a3,
                                         unsigned b0, unsigned b1) {
    asm volatile("mma.sync.aligned.m16n8k16.row.col.f32.bf16.bf16.f32 "
                 "{%0,%1,%2,%3},{%4,%5,%6,%7},{%8,%9},{%0,%1,%2,%3};"
                 : "+f"(c0), "+f"(c1), "+f"(c2), "+f"(c3)
                 : "r"(a0), "r"(a1), "r"(a2), "r"(a3), "r"(b0), "r"(b1));
}

#define AP_STRIDE 132   // padded k2-row stride (words) for aHi/aLo

__global__ void __launch_bounds__(256) sim_kernel(
    const float* __restrict__ dw,
    const float* __restrict__ X0, const float* __restrict__ R0,
    const float* __restrict__ pW1, const float* __restrict__ pb1,
    const float* __restrict__ pW2, const float* __restrict__ pb2,
    const float* __restrict__ pW3, const float* __restrict__ pb3,
    const float* __restrict__ qW1, const float* __restrict__ qb1,
    const float* __restrict__ qW2, const float* __restrict__ qb2,
    const float* __restrict__ qW3, const float* __restrict__ qb3,
    float* __restrict__ out)
{
    __shared__ __align__(16) float4   sW1q[HID];            // {w_t, w_x, w_r, b1}
    __shared__ __align__(16) unsigned aHi[32 * AP_STRIDE];  // bf16x2 h-hi, [k2][sample]
    __shared__ __align__(16) unsigned aLo[32 * AP_STRIDE];  // bf16x2 h-lo
    __shared__ __align__(16) float    part[128 * 8];        // [sample][warp]
    __shared__ float2 sxr[128];                             // {x, Rv} per sample
    __shared__ float  ph1[HID], pd1[HID], ptA[HID], ptB[HID];
    __shared__ float  s_p0, s_dp0, s_pi0, s_b3;
    __shared__ float  redA[4], redB[4];

    const int tid  = threadIdx.x;
    const int lane = tid & 31;
    const int w    = tid >> 5;         // warp id 0..7 (owns output j-tile 8w..8w+7)
    const int g    = lane >> 2;        // mma group id 0..7
    const int tg   = lane & 3;         // mma thread-in-group 0..3

    const float x0v = X0[0], r0v = R0[0];

    // ---- stage W1/b1 ----
    for (int k = tid; k < HID; k += 256)
        sW1q[k] = make_float4(qW1[k], qW1[HID + k], qW1[2 * HID + k], qb1[k]);
    if (tid == 0) s_b3 = qb3[0];

    // ---- B fragments (W2 split hi/lo) persistent in registers ----
    // warp w, lane (g,tg): j0 = 8w+2tg? NO: B frag n index = g, k from tg.
    // b0 = {W2[k0][n], W2[k0+1][n]}, b1 = {W2[k0+8][n], W2[k0+9][n]}, k0=16kt+2tg, n=8w+g
    unsigned bHi0[4], bHi1[4], bLo0[4], bLo1[4];
    {
        int n = 8 * w + g;
        #pragma unroll
        for (int kt = 0; kt < 4; ++kt) {
            int k0 = 16 * kt + 2 * tg;
            float w00 = qW2[(k0 + 0) * HID + n];
            float w01 = qW2[(k0 + 1) * HID + n];
            float w10 = qW2[(k0 + 8) * HID + n];
            float w11 = qW2[(k0 + 9) * HID + n];
            float h00 = __bfloat162float(__float2bfloat16(w00));
            float h01 = __bfloat162float(__float2bfloat16(w01));
            float h10 = __bfloat162float(__float2bfloat16(w10));
            float h11 = __bfloat162float(__float2bfloat16(w11));
            bHi0[kt] = pack_bf2(h00, h01);
            bHi1[kt] = pack_bf2(h10, h11);
            bLo0[kt] = pack_bf2(w00 - h00, w01 - h01);
            bLo1[kt] = pack_bf2(w10 - h10, w11 - h11);
        }
    }
    // epilogue constants per lane: columns j0 = 8w+2tg, j0+1
    const int jc = 8 * w + 2 * tg;
    const float b2j0 = qb2[jc], b2j1 = qb2[jc + 1];
    const float w3j0 = qW3[jc], w3j1 = qW3[jc + 1];

    // ---- scalar prep (p0, dp0, pi0), threads 0..63, exact tanh ----
    if (tid < HID) {
        int j = tid;
        float a = pW1[HID + j] * x0v + pW1[2 * HID + j] * r0v + pb1[j];
        float h = exact_tanh(a);
        ph1[j] = h;
        pd1[j] = (1.0f - h * h) * pW1[HID + j];
        float aq = qW1[HID + j] * x0v + qW1[2 * HID + j] * r0v + qb1[j];
        ptA[j] = exact_tanh(aq);
    }
    __syncthreads();
    float pa = 0.0f, qa = 0.0f, db = 0.0f;
    if (tid < HID) {
        int j = tid;
        float acc = pb2[j], dacc = 0.0f, accq = qb2[j];
        #pragma unroll 16
        for (int k = 0; k < HID; ++k) {
            float wv = pW2[k * HID + j];
            acc  += ph1[k] * wv;
            dacc += pd1[k] * wv;
            accq += ptA[k] * qW2[k * HID + j];
        }
        float h2 = exact_tanh(acc);
        float d2 = (1.0f - h2 * h2) * dacc;
        pa = h2 * pW3[j];
        db = d2 * pW3[j];
        qa = exact_tanh(accq) * qW3[j];
    }
    __syncthreads();
    if (tid < HID) { ph1[tid] = pa; pd1[tid] = qa; ptB[tid] = db; }
    __syncthreads();
    if (tid == 0) {
        float s = pb3[0], sd = 0.0f, sq = qb3[0];
        for (int k = 0; k < HID; ++k) { s += ph1[k]; sd += ptB[k]; sq += pd1[k]; }
        s_p0 = s; s_dp0 = sd; s_pi0 = sq;
    }
    __syncthreads();

    const float p0  = s_p0;
    const float dp0 = s_dp0;
    const float pi0 = s_pi0;
    const float b3v = s_b3;

    // model constants
    const float C_ADT  = 0.05f * 0.01f;
    const float C_STDT = 0.2f * 0.3f * 0.01f;
    const float SIG    = 0.2f;
    const float BEFF   = 0.1f;
    const float C_R1   = 0.02f - 0.5f * 0.1f * 0.1f;
    const float C_P1   = -(0.05f + 0.5f * 0.3f * 0.3f);
    const float TH     = 0.3f;

    // owner-thread state (t < 128: sample t)
    const int b = blockIdx.x * 128 + tid;     // valid for tid<128
    float x = x0v, mn = x0v, Wsum = 0.0f, pi = pi0, Rv = r0v, p = p0, dwv = 0.0f;
    if (tid < 128) {
        dwv = dw[b * NSTEPS];     // prefetch step-1 increment
        unsigned base = (unsigned)b * 5u;
        out[base + 0] = x0v; out[base + 1] = r0v; out[base + 2] = pi0;
        out[base + 3] = -p0; out[base + 4] = -dp0;
    }

    const int sA    = tid >> 1;         // phase-A sample
    const int halfk = tid & 1;          // phase-A k-half (units 32*halfk..+31)

    #pragma unroll 1
    for (int i = 1; i < NSTEPS; ++i) {
        float t = (float)i * DT;
        // ---- B0: state update (owner threads) ----
        if (tid < 128) {
            float dwi = dwv;
            x = x + x * C_ADT + pi * C_STDT + pi * SIG * dwi;
            mn = fminf(mn, x);
            Wsum += dwi;
            Rv = r0v * __expf(C_R1 * t + BEFF * Wsum);
            p  = p0  * __expf(C_P1 * t - TH * Wsum);
            sxr[tid] = make_float2(x, Rv);
            dwv = dw[b * NSTEPS + i];   // prefetch next
        }
        __syncthreads();

        // ---- A: hidden layer, pack bf16 hi/lo into shared ----
        {
            float2 xr = sxr[sA];
            float s0 = 2.0f * t;
            #pragma unroll
            for (int k2 = 0; k2 < 16; ++k2) {
                int k = 32 * halfk + 2 * k2;
                float4 wa = sW1q[k];
                float4 wb = sW1q[k + 1];
                float a0 = fmaf(wa.x, s0, wa.w); a0 = fmaf(wa.y, xr.x, a0); a0 = fmaf(wa.z, xr.y, a0);
                float a1 = fmaf(wb.x, s0, wb.w); a1 = fmaf(wb.y, xr.x, a1); a1 = fmaf(wb.z, xr.y, a1);
                float h0 = tanh_ap(a0), h1v = tanh_ap(a1);
                float h0h = __bfloat162float(__float2bfloat16(h0));
                float h1h = __bfloat162float(__float2bfloat16(h1v));
                int idx = (16 * halfk + k2) * AP_STRIDE + sA;
                aHi[idx] = pack_bf2(h0h, h1h);
                aLo[idx] = pack_bf2(h0 - h0h, h1v - h1h);
            }
        }
        __syncthreads();

        // ---- GEMM via mma + epilogue ----
        #pragma unroll 1
        for (int mt = 0; mt < 8; ++mt) {
            float c0 = 0.0f, c1 = 0.0f, c2 = 0.0f, c3 = 0.0f;
            #pragma unroll
            for (int kt = 0; kt < 4; ++kt) {
                int r0i = (8 * kt + tg) * AP_STRIDE + 16 * mt + g;
                int r1i = (8 * kt + tg + 4) * AP_STRIDE + 16 * mt + g;
                unsigned a0h = aHi[r0i], a1h = aHi[r0i + 8];
                unsigned a2h = aHi[r1i], a3h = aHi[r1i + 8];
                unsigned a0l = aLo[r0i], a1l = aLo[r0i + 8];
                unsigned a2l = aLo[r1i], a3l = aLo[r1i + 8];
                mma_bf16(c0, c1, c2, c3, a0h, a1h, a2h, a3h, bHi0[kt], bHi1[kt]);
                mma_bf16(c0, c1, c2, c3, a0h, a1h, a2h, a3h, bLo0[kt], bLo1[kt]);
                mma_bf16(c0, c1, c2, c3, a0l, a1l, a2l, a3l, bHi0[kt], bHi1[kt]);
            }
            // rows: rlo = 16mt+g, rhi = +8 ; cols jc, jc+1
            float v0 = fmaf(tanh_ap(c0 + b2j0), w3j0, tanh_ap(c1 + b2j1) * w3j1);
            float v1 = fmaf(tanh_ap(c2 + b2j0), w3j0, tanh_ap(c3 + b2j1) * w3j1);
            v0 += __shfl_xor_sync(0xffffffffu, v0, 1);
            v1 += __shfl_xor_sync(0xffffffffu, v1, 1);
            v0 += __shfl_xor_sync(0xffffffffu, v0, 2);
            v1 += __shfl_xor_sync(0xffffffffu, v1, 2);
            if (tg == 0) {
                part[(16 * mt + g) * 8 + w]     = v0;
                part[(16 * mt + g + 8) * 8 + w] = v1;
            }
        }
        __syncthreads();

        // ---- B1: gather pi, store outputs ----
        if (tid < 128) {
            const float4* pr = reinterpret_cast<const float4*>(part + tid * 8);
            float4 q0 = pr[0], q1 = pr[1];
            pi = b3v + ((q0.x + q0.y) + (q0.z + q0.w))
                     + ((q1.x + q1.y) + (q1.z + q1.w));
            unsigned base = ((unsigned)i * BATCH + (unsigned)b) * 5u;
            out[base + 0] = x;  out[base + 1] = Rv; out[base + 2] = pi;
            out[base + 3] = -p; out[base + 4] = -dp0;
        }
    }

    // ---- final step (i = NSTEPS): state update only, pi unchanged ----
    if (tid < 128) {
        float t = (float)NSTEPS * DT;
        float dwi = dwv;
        x = x + x * C_ADT + pi * C_STDT + pi * SIG * dwi;
        mn = fminf(mn, x);
        Wsum += dwi;
        Rv = r0v * __expf(C_R1 * t + BEFF * Wsum);
        p  = p0  * __expf(C_P1 * t - TH * Wsum);
        unsigned base = ((unsigned)NSTEPS * BATCH + (unsigned)b) * 5u;
        out[base + 0] = x;  out[base + 1] = Rv; out[base + 2] = pi;
        out[base + 3] = -p; out[base + 4] = -dp0;
    }

    // ---- losses ----
    float aa = 0.0f, bb = 0.0f;
    if (tid < 128) {
        float xc  = fmaxf(x, 1e-6f);
        float ux  = Rv * rsqrtf(xc);
        float uv  = 2.0f * Rv * sqrtf(xc);
        float dpn = fmaxf(1e-6f - mn, 0.0f);
        float pen = 100.0f * dpn * dpn;
        aa = p + ux; aa = aa * aa + pen;
        bb = -uv + pen;
    }
    if (tid < 128) {
        #pragma unroll
        for (int s = 16; s > 0; s >>= 1) {
            aa += __shfl_xor_sync(0xffffffffu, aa, s);
            bb += __shfl_xor_sync(0xffffffffu, bb, s);
        }
        if (lane == 0) { redA[w] = aa; redB[w] = bb; }
    }
    __syncthreads();
    if (tid == 0) {
        float sA2 = (redA[0] + redA[1]) + (redA[2] + redA[3]);
        float sB2 = (redB[0] + redB[1]) + (redB[2] + redB[3]);
        g_pA[blockIdx.x] = sA2; g_pB[blockIdx.x] = sB2;
    }
}

__global__ void finalize_kernel(float* __restrict__ out)
{
    __shared__ float rA[128], rB[128];
    int tid = threadIdx.x;
    rA[tid] = g_pA[tid]; rB[tid] = g_pB[tid];
    __syncthreads();
    for (int s = 64; s > 0; s >>= 1) {
        if (tid < s) { rA[tid] += rA[tid + s]; rB[tid] += rB[tid + s]; }
        __syncthreads();
    }
    if (tid == 0) {
        float lp  = rA[0] / (float)BATCH;
        float lpi = lp + rB[0] / (float)BATCH;
        unsigned base = (unsigned)(NSTEPS + 1) * BATCH * 5u;
        out[base + 0] = lp;
        out[base + 1] = lpi;
    }
}

extern "C" void kernel_launch(void* const* d_in, const int* in_sizes, int n_in,
                              void* d_out, int out_size)
{
    const float* dw  = (const float*)d_in[0];
    const float* X0  = (const float*)d_in[1];
    const float* R0  = (const float*)d_in[2];
    const float* pW1 = (const float*)d_in[3];  const float* pb1 = (const float*)d_in[4];
    const float* pW2 = (const float*)d_in[5];  const float* pb2 = (const float*)d_in[6];
    const float* pW3 = (const float*)d_in[7];  const float* pb3 = (const float*)d_in[8];
    const float* qW1 = (const float*)d_in[9];  const float* qb1 = (const float*)d_in[10];
    const float* qW2 = (const float*)d_in[11]; const float* qb2 = (const float*)d_in[12];
    const float* qW3 = (const float*)d_in[13]; const float* qb3 = (const float*)d_in[14];
    float* out = (float*)d_out;

    sim_kernel<<<128, 256>>>(dw, X0, R0, pW1, pb1, pW2, pb2, pW3, pb3,
                             qW1, qb1, qW2, qb2, qW3, qb3, out);
    finalize_kernel<<<1, 128>>>(out);
}

// round 6
// speedup vs baseline: 2.5399x; 1.6772x over previous
#include <cuda_runtime.h>
#include <cuda_bf16.h>

#define HID    64
#define BATCH  16384
#define NSTEPS 100
#define DT     0.01f
#define AP_STRIDE 132   // padded k2-row stride (words) for aHi/aLo

__device__ float g_pA[128];
__device__ float g_pB[128];

__device__ __forceinline__ float exact_tanh(float v) {
    float av = fabsf(v);
    float e  = __expf(-2.0f * av);
    float r  = __fdividef(1.0f - e, 1.0f + e);
    return copysignf(r, v);
}
__device__ __forceinline__ float tanh_ap(float x) {
    float y; asm("tanh.approx.f32 %0, %1;" : "=f"(y) : "f"(x)); return y;
}
__device__ __forceinline__ unsigned pack_bf2(float lo, float hi) {
    __nv_bfloat162 v = __floats2bfloat162_rn(lo, hi);
    return *reinterpret_cast<unsigned*>(&v);
}
__device__ __forceinline__ void mma_bf16(float* c,
                                         unsigned a0, unsigned a1, unsigned a2, unsigned a3,
                                         unsigned b0, unsigned b1) {
    asm volatile("mma.sync.aligned.m16n8k16.row.col.f32.bf16.bf16.f32 "
                 "{%0,%1,%2,%3},{%4,%5,%6,%7},{%8,%9},{%0,%1,%2,%3};"
                 : "+f"(c[0]), "+f"(c[1]), "+f"(c[2]), "+f"(c[3])
                 : "r"(a0), "r"(a1), "r"(a2), "r"(a3), "r"(b0), "r"(b1));
}

__global__ void __launch_bounds__(256) sim_kernel(
    const float* __restrict__ dw,
    const float* __restrict__ X0, const float* __restrict__ R0,
    const float* __restrict__ pW1, const float* __restrict__ pb1,
    const float* __restrict__ pW2, const float* __restrict__ pb2,
    const float* __restrict__ pW3, const float* __restrict__ pb3,
    const float* __restrict__ qW1, const float* __restrict__ qb1,
    const float* __restrict__ qW2, const float* __restrict__ qb2,
    const float* __restrict__ qW3, const float* __restrict__ qb3,
    float* __restrict__ out)
{
    __shared__ __align__(16) float4   sW1q[HID];            // {w_t, w_x, w_r, b1}
    __shared__ __align__(16) unsigned aHi[32 * AP_STRIDE];  // bf16x2 h-hi [k2][sample]
    __shared__ __align__(16) unsigned aLo[32 * AP_STRIDE];  // bf16x2 h-lo
    __shared__ __align__(16) float    part[128 * 4];        // [sample][ng] (2 used)
    __shared__ float2 sxr[128];
    __shared__ float  ph1[HID], pd1[HID], ptA[HID], ptB[HID];
    __shared__ float  s_p0, s_dp0, s_pi0, s_b3;
    __shared__ float  redA[4], redB[4];

    const int tid  = threadIdx.x;
    const int lane = tid & 31;
    const int w    = tid >> 5;
    const int g    = lane >> 2;
    const int tg   = lane & 3;
    const int mg   = w >> 1;           // m-group: rows 32mg..32mg+31
    const int ng   = w & 1;            // n-group: cols 32ng..32ng+31

    const float x0v = X0[0], r0v = R0[0];

    for (int k = tid; k < HID; k += 256)
        sW1q[k] = make_float4(qW1[k], qW1[HID + k], qW1[2 * HID + k], qb1[k]);
    if (tid == 0) s_b3 = qb3[0];

    // ---- B fragments (W2 split hi/lo), persistent in registers ----
    // [nt][kt]: n = 32ng+8nt+g, k0 = 16kt+2tg
    unsigned bH0[4][4], bH1[4][4], bL0[4][4], bL1[4][4];
    float b2a[4], b2b[4], w3a[4], w3b[4];
    #pragma unroll
    for (int nt = 0; nt < 4; ++nt) {
        int n = 32 * ng + 8 * nt + g;
        #pragma unroll
        for (int kt = 0; kt < 4; ++kt) {
            int k0 = 16 * kt + 2 * tg;
            float w00 = qW2[(k0 + 0) * HID + n];
            float w01 = qW2[(k0 + 1) * HID + n];
            float w10 = qW2[(k0 + 8) * HID + n];
            float w11 = qW2[(k0 + 9) * HID + n];
            float h00 = __bfloat162float(__float2bfloat16(w00));
            float h01 = __bfloat162float(__float2bfloat16(w01));
            float h10 = __bfloat162float(__float2bfloat16(w10));
            float h11 = __bfloat162float(__float2bfloat16(w11));
            bH0[nt][kt] = pack_bf2(h00, h01);
            bH1[nt][kt] = pack_bf2(h10, h11);
            bL0[nt][kt] = pack_bf2(w00 - h00, w01 - h01);
            bL1[nt][kt] = pack_bf2(w10 - h10, w11 - h11);
        }
        int jc = 32 * ng + 8 * nt + 2 * tg;
        b2a[nt] = qb2[jc];     b2b[nt] = qb2[jc + 1];
        w3a[nt] = qW3[jc];     w3b[nt] = qW3[jc + 1];
    }

    // ---- scalar prep (p0, dp0, pi0), exact tanh ----
    if (tid < HID) {
        int j = tid;
        float a = pW1[HID + j] * x0v + pW1[2 * HID + j] * r0v + pb1[j];
        float h = exact_tanh(a);
        ph1[j] = h;
        pd1[j] = (1.0f - h * h) * pW1[HID + j];
        float aq = qW1[HID + j] * x0v + qW1[2 * HID + j] * r0v + qb1[j];
        ptA[j] = exact_tanh(aq);
    }
    __syncthreads();
    float pa = 0.0f, qa = 0.0f, db = 0.0f;
    if (tid < HID) {
        int j = tid;
        float acc = pb2[j], dacc = 0.0f, accq = qb2[j];
        #pragma unroll 16
        for (int k = 0; k < HID; ++k) {
            float wv = pW2[k * HID + j];
            acc  += ph1[k] * wv;
            dacc += pd1[k] * wv;
            accq += ptA[k] * qW2[k * HID + j];
        }
        float h2 = exact_tanh(acc);
        float d2 = (1.0f - h2 * h2) * dacc;
        pa = h2 * pW3[j];
        db = d2 * pW3[j];
        qa = exact_tanh(accq) * qW3[j];
    }
    __syncthreads();
    if (tid < HID) { ph1[tid] = pa; pd1[tid] = qa; ptB[tid] = db; }
    __syncthreads();
    if (tid == 0) {
        float s = pb3[0], sd = 0.0f, sq = qb3[0];
        for (int k = 0; k < HID; ++k) { s += ph1[k]; sd += ptB[k]; sq += pd1[k]; }
        s_p0 = s; s_dp0 = sd; s_pi0 = sq;
    }
    __syncthreads();

    const float p0  = s_p0;
    const float dp0 = s_dp0;
    const float pi0 = s_pi0;
    const float b3v = s_b3;

    const float C_ADT  = 0.05f * 0.01f;
    const float C_STDT = 0.2f * 0.3f * 0.01f;
    const float SIG    = 0.2f;
    const float BEFF   = 0.1f;
    const float C_R1   = 0.02f - 0.5f * 0.1f * 0.1f;
    const float C_P1   = -(0.05f + 0.5f * 0.3f * 0.3f);
    const float TH     = 0.3f;

    const int b = blockIdx.x * 128 + tid;     // valid for tid<128
    float x = x0v, mn = x0v, Wsum = 0.0f, pi = pi0, Rv = r0v, p = p0, dwv = 0.0f;
    if (tid < 128) {
        dwv = dw[b * NSTEPS];
        unsigned base = (unsigned)b * 5u;
        out[base + 0] = x0v; out[base + 1] = r0v; out[base + 2] = pi0;
        out[base + 3] = -p0; out[base + 4] = -dp0;
    }

    const int sA    = tid >> 1;
    const int halfk = tid & 1;

    #pragma unroll 1
    for (int i = 1; i < NSTEPS; ++i) {
        float t = (float)i * DT;
        // ---- O: gather pi (prev GEMM), store prev row, advance state ----
        if (tid < 128) {
            if (i > 1) {
                float2 pr = *reinterpret_cast<const float2*>(part + tid * 4);
                pi = b3v + pr.x + pr.y;
                unsigned base = ((unsigned)(i - 1) * BATCH + (unsigned)b) * 5u;
                out[base + 0] = x;  out[base + 1] = Rv; out[base + 2] = pi;
                out[base + 3] = -p; out[base + 4] = -dp0;
            }
            float dwi = dwv;
            x = x + x * C_ADT + pi * C_STDT + pi * SIG * dwi;
            mn = fminf(mn, x);
            Wsum += dwi;
            Rv = r0v * __expf(C_R1 * t + BEFF * Wsum);
            p  = p0  * __expf(C_P1 * t - TH * Wsum);
            sxr[tid] = make_float2(x, Rv);
            dwv = dw[b * NSTEPS + i];
        }
        __syncthreads();

        // ---- A: hidden layer -> bf16 hi/lo in shared ----
        {
            float2 xr = sxr[sA];
            float s0 = 2.0f * t;
            #pragma unroll
            for (int k2 = 0; k2 < 16; ++k2) {
                int k = 32 * halfk + 2 * k2;
                float4 wa = sW1q[k];
                float4 wb = sW1q[k + 1];
                float a0 = fmaf(wa.x, s0, wa.w); a0 = fmaf(wa.y, xr.x, a0); a0 = fmaf(wa.z, xr.y, a0);
                float a1 = fmaf(wb.x, s0, wb.w); a1 = fmaf(wb.y, xr.x, a1); a1 = fmaf(wb.z, xr.y, a1);
                float h0 = tanh_ap(a0), h1v = tanh_ap(a1);
                float h0h = __bfloat162float(__float2bfloat16(h0));
                float h1h = __bfloat162float(__float2bfloat16(h1v));
                int idx = (16 * halfk + k2) * AP_STRIDE + sA;
                aHi[idx] = pack_bf2(h0h, h1h);
                aLo[idx] = pack_bf2(h0 - h0h, h1v - h1h);
            }
        }
        __syncthreads();

        // ---- GEMM: warp tile 32 rows x 32 cols ----
        {
            float c[2][4][4];
            #pragma unroll
            for (int m2 = 0; m2 < 2; ++m2)
                #pragma unroll
                for (int nt = 0; nt < 4; ++nt)
                    #pragma unroll
                    for (int q = 0; q < 4; ++q) c[m2][nt][q] = 0.0f;

            #pragma unroll
            for (int kt = 0; kt < 4; ++kt) {
                #pragma unroll
                for (int m2 = 0; m2 < 2; ++m2) {
                    int base = 32 * mg + 16 * m2;
                    int r0i = (8 * kt + tg) * AP_STRIDE + base + g;
                    int r1i = (8 * kt + tg + 4) * AP_STRIDE + base + g;
                    unsigned a0h = aHi[r0i], a1h = aHi[r0i + 8];
                    unsigned a2h = aHi[r1i], a3h = aHi[r1i + 8];
                    unsigned a0l = aLo[r0i], a1l = aLo[r0i + 8];
                    unsigned a2l = aLo[r1i], a3l = aLo[r1i + 8];
                    #pragma unroll
                    for (int nt = 0; nt < 4; ++nt) {
                        mma_bf16(c[m2][nt], a0h, a1h, a2h, a3h, bH0[nt][kt], bH1[nt][kt]);
                        mma_bf16(c[m2][nt], a0h, a1h, a2h, a3h, bL0[nt][kt], bL1[nt][kt]);
                        mma_bf16(c[m2][nt], a0l, a1l, a2l, a3l, bH0[nt][kt], bH1[nt][kt]);
                    }
                }
            }
            // epilogue: tanh, W3 dot, reduce over tg
            #pragma unroll
            for (int m2 = 0; m2 < 2; ++m2) {
                float vl = 0.0f, vh = 0.0f;
                #pragma unroll
                for (int nt = 0; nt < 4; ++nt) {
                    vl += fmaf(tanh_ap(c[m2][nt][0] + b2a[nt]), w3a[nt],
                               tanh_ap(c[m2][nt][1] + b2b[nt]) * w3b[nt]);
                    vh += fmaf(tanh_ap(c[m2][nt][2] + b2a[nt]), w3a[nt],
                               tanh_ap(c[m2][nt][3] + b2b[nt]) * w3b[nt]);
                }
                vl += __shfl_xor_sync(0xffffffffu, vl, 1);
                vh += __shfl_xor_sync(0xffffffffu, vh, 1);
                vl += __shfl_xor_sync(0xffffffffu, vl, 2);
                vh += __shfl_xor_sync(0xffffffffu, vh, 2);
                if (tg == 0) {
                    int base = 32 * mg + 16 * m2;
                    part[(base + g) * 4 + ng]     = vl;
                    part[(base + g + 8) * 4 + ng] = vh;
                }
            }
        }
        __syncthreads();
    }

    // ---- tail: gather pi at t_99, store row 99; final step to t_100 ----
    if (tid < 128) {
        {
            float2 pr = *reinterpret_cast<const float2*>(part + tid * 4);
            pi = b3v + pr.x + pr.y;
            unsigned base = ((unsigned)(NSTEPS - 1) * BATCH + (unsigned)b) * 5u;
            out[base + 0] = x;  out[base + 1] = Rv; out[base + 2] = pi;
            out[base + 3] = -p; out[base + 4] = -dp0;
        }
        float t = (float)NSTEPS * DT;
        float dwi = dwv;
        x = x + x * C_ADT + pi * C_STDT + pi * SIG * dwi;
        mn = fminf(mn, x);
        Wsum += dwi;
        Rv = r0v * __expf(C_R1 * t + BEFF * Wsum);
        p  = p0  * __expf(C_P1 * t - TH * Wsum);
        unsigned base = ((unsigned)NSTEPS * BATCH + (unsigned)b) * 5u;
        out[base + 0] = x;  out[base + 1] = Rv; out[base + 2] = pi;
        out[base + 3] = -p; out[base + 4] = -dp0;
    }

    // ---- losses ----
    float aa = 0.0f, bb = 0.0f;
    if (tid < 128) {
        float xc  = fmaxf(x, 1e-6f);
        float ux  = Rv * rsqrtf(xc);
        float uv  = 2.0f * Rv * sqrtf(xc);
        float dpn = fmaxf(1e-6f - mn, 0.0f);
        float pen = 100.0f * dpn * dpn;
        aa = p + ux; aa = aa * aa + pen;
        bb = -uv + pen;
        #pragma unroll
        for (int s = 16; s > 0; s >>= 1) {
            aa += __shfl_xor_sync(0xffffffffu, aa, s);
            bb += __shfl_xor_sync(0xffffffffu, bb, s);
        }
        if (lane == 0) { redA[w] = aa; redB[w] = bb; }
    }
    __syncthreads();
    if (tid == 0) {
        float sA2 = (redA[0] + redA[1]) + (redA[2] + redA[3]);
        float sB2 = (redB[0] + redB[1]) + (redB[2] + redB[3]);
        g_pA[blockIdx.x] = sA2; g_pB[blockIdx.x] = sB2;
    }
}

__global__ void finalize_kernel(float* __restrict__ out)
{
    __shared__ float rA[128], rB[128];
    int tid = threadIdx.x;
    rA[tid] = g_pA[tid]; rB[tid] = g_pB[tid];
    __syncthreads();
    for (int s = 64; s > 0; s >>= 1) {
        if (tid < s) { rA[tid] += rA[tid + s]; rB[tid] += rB[tid + s]; }
        __syncthreads();
    }
    if (tid == 0) {
        float lp  = rA[0] / (float)BATCH;
        float lpi = lp + rB[0] / (float)BATCH;
        unsigned base = (unsigned)(NSTEPS + 1) * BATCH * 5u;
        out[base + 0] = lp;
        out[base + 1] = lpi;
    }
}

extern "C" void kernel_launch(void* const* d_in, const int* in_sizes, int n_in,
                              void* d_out, int out_size)
{
    const float* dw  = (const float*)d_in[0];
    const float* X0  = (const float*)d_in[1];
    const float* R0  = (const float*)d_in[2];
    const float* pW1 = (const float*)d_in[3];  const float* pb1 = (const float*)d_in[4];
    const float* pW2 = (const float*)d_in[5];  const float* pb2 = (const float*)d_in[6];
    const float* pW3 = (const float*)d_in[7];  const float* pb3 = (const float*)d_in[8];
    const float* qW1 = (const float*)d_in[9];  const float* qb1 = (const float*)d_in[10];
    const float* qW2 = (const float*)d_in[11]; const float* qb2 = (const float*)d_in[12];
    const float* qW3 = (const float*)d_in[13]; const float* qb3 = (const float*)d_in[14];
    float* out = (float*)d_out;

    sim_kernel<<<128, 256>>>(dw, X0, R0, pW1, pb1, pW2, pb2, pW3, pb3,
                             qW1, qb1, qW2, qb2, qW3, qb3, out);
    finalize_kernel<<<1, 128>>>(out);
}